// round 8
// baseline (speedup 1.0000x reference)
#include <cuda_runtime.h>
#include <stdint.h>
#include <math.h>

// Problem shape (fixed by setup_inputs in the reference):
//   CB  : [B, L, 3] f32      (d_in[0])
//   mask: [B, L]    f32      (d_in[1])
//   Y   : [B, M, 3] f32      (d_in[2])
//   Y_t : [B, M]    i32      (d_in[3])
//   Y_m : [B, M]    i32      (d_in[4])
//   number_of_ligand_atoms = 25 (scalar, d_in[5], hardcoded here)
//
// Outputs (flattened + concatenated, f32):
//   Y_out       [B, L, K, 3]
//   Y_t_out     [B, L, K]
//   Y_m_out     [B, L, K]
//   D_AB_closest[B, L]

#define BB 8
#define LL 2048
#define MM 4096
#define KSEL 25
#define NTHREADS 256
#define NC (MM / NTHREADS)   // 16 candidates per thread

__device__ __forceinline__ unsigned long long u64min(unsigned long long a,
                                                     unsigned long long b) {
    return a < b ? a : b;
}

__global__ __launch_bounds__(NTHREADS, 4)
void knn25_kernel(const float* __restrict__ CB,
                  const float* __restrict__ mask,
                  const float* __restrict__ Y,
                  const int*   __restrict__ Yt,
                  const int*   __restrict__ Ym,
                  float* __restrict__ out)
{
    // double-buffered cross-warp exchange: one barrier per extraction round
    __shared__ unsigned long long wbuf[2][NTHREADS / 32];

    const int row  = blockIdx.x;          // b * LL + l
    const int b    = row >> 11;           // LL = 2048
    const int tid  = threadIdx.x;
    const int warp = tid >> 5;
    const int lane = tid & 31;

    // broadcast loads (all threads same address -> L1 broadcast)
    const float cbx = CB[row * 3 + 0];
    const float cby = CB[row * 3 + 1];
    const float cbz = CB[row * 3 + 2];
    const float mk  = mask[row];

    const float* __restrict__ Yb  = Y  + (size_t)b * MM * 3;
    const int*   __restrict__ Ymb = Ym + b * MM;
    const int*   __restrict__ Ytb = Yt + b * MM;

    // ---- Phase 1: compute packed keys into registers, track local min ----
    // key = (float_bits(d2_eff) << 32) | m  ; float_bits monotone for d2>=0,
    // low bits break ties by smaller index m — exactly jax.lax.top_k order.
    unsigned long long key[NC];
    unsigned long long lk = ~0ull;
    const bool row_valid = (mk != 0.0f);

    #pragma unroll
    for (int i = 0; i < NC; i++) {
        const int m = tid + (i << 8);          // coalesced: stride-256 per thread
        const float yx = Yb[m * 3 + 0];
        const float yy = Yb[m * 3 + 1];
        const float yz = Yb[m * 3 + 2];
        const int   ym = Ymb[m];
        const float dx = cbx - yx;
        const float dy = cby - yy;
        const float dz = cbz - yz;
        const float d2 = fmaf(dx, dx, fmaf(dy, dy, dz * dz));
        const float d2e = (row_valid && ym != 0) ? d2 : 1000.0f;
        const unsigned long long kk =
            ((unsigned long long)__float_as_uint(d2e) << 32) | (unsigned)m;
        key[i] = kk;
        lk = u64min(lk, kk);
    }

    // ---- Phase 2: 25 extraction rounds (register tournament) ----
    unsigned long long mykey = 0;  // winner of round == tid (valid for tid < KSEL)

    for (int r = 0; r < KSEL; r++) {
        // warp-level u64 min of current local minima
        unsigned long long w = lk;
        #pragma unroll
        for (int s = 16; s > 0; s >>= 1) {
            unsigned long long o = __shfl_xor_sync(0xffffffffu, w, s);
            w = u64min(w, o);
        }
        if (lane == 0) wbuf[r & 1][warp] = w;
        __syncthreads();

        // every thread reduces the 8 warp results (broadcast reads, cheap)
        unsigned long long g = wbuf[r & 1][0];
        #pragma unroll
        for (int j = 1; j < NTHREADS / 32; j++) g = u64min(g, wbuf[r & 1][j]);

        if (tid == r) mykey = g;

        // exactly one thread owns the winning key (index m is embedded):
        // consume it and recompute its local min from registers only.
        if (lk == g) {
            lk = ~0ull;
            #pragma unroll
            for (int i = 0; i < NC; i++) {
                if (key[i] == g) key[i] = ~0ull;
                lk = u64min(lk, key[i]);
            }
        }
    }

    // ---- Phase 3: parallel gather + store (threads 0..24) ----
    if (tid < KSEL) {
        const int   m  = (unsigned)mykey;                       // low 32 bits
        const float d2 = __uint_as_float((unsigned)(mykey >> 32));

        const size_t po   = (size_t)row * KSEL + tid;
        const size_t OFF1 = (size_t)BB * LL * KSEL * 3;         // after Y_out
        const size_t OFF2 = OFF1 + (size_t)BB * LL * KSEL;      // after Y_t_out
        const size_t OFF3 = OFF2 + (size_t)BB * LL * KSEL;      // after Y_m_out

        out[po * 3 + 0] = Yb[m * 3 + 0];
        out[po * 3 + 1] = Yb[m * 3 + 1];
        out[po * 3 + 2] = Yb[m * 3 + 2];
        out[OFF1 + po]  = (float)Ytb[m];
        out[OFF2 + po]  = (float)Ymb[m];
        if (tid == 0) out[OFF3 + row] = sqrtf(d2);
    }
}

extern "C" void kernel_launch(void* const* d_in, const int* in_sizes, int n_in,
                              void* d_out, int out_size)
{
    (void)in_sizes; (void)n_in; (void)out_size;
    const float* CB   = (const float*)d_in[0];
    const float* mask = (const float*)d_in[1];
    const float* Y    = (const float*)d_in[2];
    const int*   Yt   = (const int*)d_in[3];
    const int*   Ym   = (const int*)d_in[4];
    float* out = (float*)d_out;

    knn25_kernel<<<BB * LL, NTHREADS>>>(CB, mask, Y, Yt, Ym, out);
}

// round 13
// speedup vs baseline: 1.1213x; 1.1213x over previous
#include <cuda_runtime.h>
#include <stdint.h>
#include <math.h>

// CB:[B,L,3] f32, mask:[B,L] f32, Y:[B,M,3] f32, Yt:[B,M] i32, Ym:[B,M] i32
// out: Y_out[B,L,K,3] ++ Y_t_out[B,L,K] ++ Y_m_out[B,L,K] ++ D[B,L]  (all f32)

#define BB 8
#define LL 2048
#define MM 4096
#define KSEL 25
#define NT 256
#define NC 16            // candidates per thread
#define NWARP 8

typedef unsigned long long u64;
typedef unsigned int u32;

__device__ __forceinline__ u64 u64min(u64 a, u64 b) { return a < b ? a : b; }

__global__ __launch_bounds__(NT, 4)
void knn25_kernel(const float* __restrict__ CB,
                  const float* __restrict__ mask,
                  const float* __restrict__ Y,
                  const int*   __restrict__ Yt,
                  const int*   __restrict__ Ym,
                  float* __restrict__ out)
{
    // double-buffered per-warp minima (64B per buffer, 16B aligned for LDS.128)
    __shared__ __align__(16) u64 wmin[2][NWARP];

    const int row  = blockIdx.x;          // b*LL + l
    const int b    = row >> 11;           // LL = 2048
    const int tid  = threadIdx.x;
    const int warp = tid >> 5;
    const int lane = tid & 31;

    const float* __restrict__ Yb  = Y  + (size_t)b * MM * 3;
    const int*   __restrict__ Ymb = Ym + b * MM;
    const int*   __restrict__ Ytb = Yt + b * MM;

    const size_t O1 = (size_t)BB * LL * KSEL * 3;
    const size_t O2 = O1 + (size_t)BB * LL * KSEL;
    const size_t O3 = O2 + (size_t)BB * LL * KSEL;

    // ---- Masked-row fast path (block-uniform; before any barrier) ----
    // mask==0  =>  all L2 = 1000  =>  top_k picks indices 0..24, D = sqrt(1000)
    if (mask[row] == 0.0f) {
        if (tid < KSEL) {
            const int m = tid;
            const size_t po = (size_t)row * KSEL + tid;
            out[po * 3 + 0] = Yb[m * 3 + 0];
            out[po * 3 + 1] = Yb[m * 3 + 1];
            out[po * 3 + 2] = Yb[m * 3 + 2];
            out[O1 + po]    = (float)Ytb[m];
            out[O2 + po]    = (float)Ymb[m];
            if (tid == 0) out[O3 + row] = sqrtf(1000.0f);
        }
        return;
    }

    const float cbx = CB[row * 3 + 0];
    const float cby = CB[row * 3 + 1];
    const float cbz = CB[row * 3 + 2];

    // ---- Phase 1: packed keys in registers + thread-local min (R8-proven) ----
    // key = (float_bits(d2_eff) << 32) | m ; monotone in d2, tie-break lower m
    u64 key[NC];
    u64 lk = ~0ull;
    #pragma unroll
    for (int i = 0; i < NC; i++) {
        const int m = tid + (i << 8);
        const float yx = Yb[m * 3 + 0];
        const float yy = Yb[m * 3 + 1];
        const float yz = Yb[m * 3 + 2];
        const int   ym = Ymb[m];
        const float dx = cbx - yx, dy = cby - yy, dz = cbz - yz;
        const float d2 = fmaf(dx, dx, fmaf(dy, dy, dz * dz));
        const float d2e = (ym != 0) ? d2 : 1000.0f;
        const u64 kk = ((u64)__float_as_uint(d2e) << 32) | (u32)m;
        key[i] = kk;
        lk = u64min(lk, kk);
    }

    // initial per-warp minima -> wmin[0]
    {
        u64 w0 = lk;
        #pragma unroll
        for (int s = 16; s > 0; s >>= 1)
            w0 = u64min(w0, __shfl_xor_sync(0xffffffffu, w0, s));
        if (lane == 0) wmin[0][warp] = w0;
    }
    __syncthreads();

    // ---- Phase 2: 25 extraction rounds, hierarchical reduce ----
    // Invariant: wmin[cur][w] = min over warp w's remaining keys.
    // One barrier per round; buffers alternate so reads never race writes.
    u64 mykey = 0;
    #pragma unroll 1
    for (int r = 0; r < KSEL; r++) {
        const int cur = r & 1;

        // global min = min of 8 cached warp minima (vectorized smem loads)
        const ulonglong2* p2 = reinterpret_cast<const ulonglong2*>(wmin[cur]);
        const ulonglong2 v0 = p2[0], v1 = p2[1], v2 = p2[2], v3 = p2[3];
        const u64 g = u64min(u64min(u64min(v0.x, v0.y), u64min(v1.x, v1.y)),
                             u64min(u64min(v2.x, v2.y), u64min(v3.x, v3.y)));

        if (tid == r) mykey = g;           // thread r keeps the r-th smallest

        // unique owner consumes (keys globally distinct: m embedded)
        const bool iwin = (lk == g);
        if (iwin) {
            lk = ~0ull;
            #pragma unroll
            for (int i = 0; i < NC; i++) {
                if (key[i] == g) key[i] = ~0ull;
                lk = u64min(lk, key[i]);
            }
        }

        // only the winning warp recomputes its minimum; others carry forward
        u64 nw;
        if (__ballot_sync(0xffffffffu, iwin)) {
            nw = lk;
            #pragma unroll
            for (int s = 16; s > 0; s >>= 1)
                nw = u64min(nw, __shfl_xor_sync(0xffffffffu, nw, s));
        } else {
            nw = wmin[cur][warp];
        }
        if (lane == 0) wmin[cur ^ 1][warp] = nw;
        __syncthreads();
    }

    // ---- Phase 3: gather + store (threads 0..24), R8-identical ----
    if (tid < KSEL) {
        const int   m  = (u32)mykey;
        const float d2 = __uint_as_float((u32)(mykey >> 32));

        const size_t po = (size_t)row * KSEL + tid;
        out[po * 3 + 0] = Yb[m * 3 + 0];
        out[po * 3 + 1] = Yb[m * 3 + 1];
        out[po * 3 + 2] = Yb[m * 3 + 2];
        out[O1 + po]    = (float)Ytb[m];
        out[O2 + po]    = (float)Ymb[m];
        if (tid == 0) out[O3 + row] = sqrtf(d2);
    }
}

extern "C" void kernel_launch(void* const* d_in, const int* in_sizes, int n_in,
                              void* d_out, int out_size)
{
    (void)in_sizes; (void)n_in; (void)out_size;
    const float* CB   = (const float*)d_in[0];
    const float* mask = (const float*)d_in[1];
    const float* Y    = (const float*)d_in[2];
    const int*   Yt   = (const int*)d_in[3];
    const int*   Ym   = (const int*)d_in[4];
    float* out = (float*)d_out;

    knn25_kernel<<<BB * LL, NT>>>(CB, mask, Y, Yt, Ym, out);
}

// round 14
// speedup vs baseline: 1.1246x; 1.0029x over previous
#include <cuda_runtime.h>
#include <stdint.h>
#include <math.h>

// CB:[B,L,3] f32, mask:[B,L] f32, Y:[B,M,3] f32, Yt:[B,M] i32, Ym:[B,M] i32
// out: Y_out[B,L,K,3] ++ Y_t_out[B,L,K] ++ Y_m_out[B,L,K] ++ D[B,L]  (all f32)

#define BB 8
#define LL 2048
#define MM 4096
#define KSEL 25
#define NT 256
#define NC 16            // candidates per thread
#define NWARP 8

typedef unsigned long long u64;
typedef unsigned int u32;

__device__ __forceinline__ u64 u64min(u64 a, u64 b) { return a < b ? a : b; }

__global__ __launch_bounds__(NT, 4)
void knn25_kernel(const float* __restrict__ CB,
                  const float* __restrict__ mask,
                  const float* __restrict__ Y,
                  const int*   __restrict__ Yt,
                  const int*   __restrict__ Ym,
                  float* __restrict__ out)
{
    // double-buffered per-warp minima (64B per buffer, 16B aligned for LDS.128)
    __shared__ __align__(16) u64 wmin[2][NWARP];

    const int row  = blockIdx.x;          // b*LL + l
    const int b    = row >> 11;           // LL = 2048
    const int tid  = threadIdx.x;
    const int warp = tid >> 5;
    const int lane = tid & 31;

    const float* __restrict__ Yb  = Y  + (size_t)b * MM * 3;
    const int*   __restrict__ Ymb = Ym + b * MM;
    const int*   __restrict__ Ytb = Yt + b * MM;

    const size_t O1 = (size_t)BB * LL * KSEL * 3;
    const size_t O2 = O1 + (size_t)BB * LL * KSEL;
    const size_t O3 = O2 + (size_t)BB * LL * KSEL;

    // ---- Masked-row fast path (block-uniform; before any barrier) ----
    // mask==0  =>  all L2 = 1000  =>  top_k picks indices 0..24, D = sqrt(1000)
    if (mask[row] == 0.0f) {
        if (tid < KSEL) {
            const int m = tid;
            const size_t po = (size_t)row * KSEL + tid;
            out[po * 3 + 0] = Yb[m * 3 + 0];
            out[po * 3 + 1] = Yb[m * 3 + 1];
            out[po * 3 + 2] = Yb[m * 3 + 2];
            out[O1 + po]    = (float)Ytb[m];
            out[O2 + po]    = (float)Ymb[m];
            if (tid == 0) out[O3 + row] = sqrtf(1000.0f);
        }
        return;
    }

    const float cbx = CB[row * 3 + 0];
    const float cby = CB[row * 3 + 1];
    const float cbz = CB[row * 3 + 2];

    // ---- Phase 1: packed keys in registers + thread-local min (R8-proven) ----
    // key = (float_bits(d2_eff) << 32) | m ; monotone in d2, tie-break lower m
    u64 key[NC];
    u64 lk = ~0ull;
    #pragma unroll
    for (int i = 0; i < NC; i++) {
        const int m = tid + (i << 8);
        const float yx = Yb[m * 3 + 0];
        const float yy = Yb[m * 3 + 1];
        const float yz = Yb[m * 3 + 2];
        const int   ym = Ymb[m];
        const float dx = cbx - yx, dy = cby - yy, dz = cbz - yz;
        const float d2 = fmaf(dx, dx, fmaf(dy, dy, dz * dz));
        const float d2e = (ym != 0) ? d2 : 1000.0f;
        const u64 kk = ((u64)__float_as_uint(d2e) << 32) | (u32)m;
        key[i] = kk;
        lk = u64min(lk, kk);
    }

    // initial per-warp minima -> wmin[0]
    {
        u64 w0 = lk;
        #pragma unroll
        for (int s = 16; s > 0; s >>= 1)
            w0 = u64min(w0, __shfl_xor_sync(0xffffffffu, w0, s));
        if (lane == 0) wmin[0][warp] = w0;
    }
    __syncthreads();

    // ---- Phase 2: 25 extraction rounds, hierarchical reduce ----
    // Invariant: wmin[cur][w] = min over warp w's remaining keys.
    // One barrier per round; buffers alternate so reads never race writes.
    u64 mykey = 0;
    #pragma unroll 1
    for (int r = 0; r < KSEL; r++) {
        const int cur = r & 1;

        // global min = min of 8 cached warp minima (vectorized smem loads)
        const ulonglong2* p2 = reinterpret_cast<const ulonglong2*>(wmin[cur]);
        const ulonglong2 v0 = p2[0], v1 = p2[1], v2 = p2[2], v3 = p2[3];
        const u64 g = u64min(u64min(u64min(v0.x, v0.y), u64min(v1.x, v1.y)),
                             u64min(u64min(v2.x, v2.y), u64min(v3.x, v3.y)));

        if (tid == r) mykey = g;           // thread r keeps the r-th smallest

        // unique owner consumes (keys globally distinct: m embedded)
        const bool iwin = (lk == g);
        if (iwin) {
            lk = ~0ull;
            #pragma unroll
            for (int i = 0; i < NC; i++) {
                if (key[i] == g) key[i] = ~0ull;
                lk = u64min(lk, key[i]);
            }
        }

        // only the winning warp recomputes its minimum; others carry forward
        u64 nw;
        if (__ballot_sync(0xffffffffu, iwin)) {
            nw = lk;
            #pragma unroll
            for (int s = 16; s > 0; s >>= 1)
                nw = u64min(nw, __shfl_xor_sync(0xffffffffu, nw, s));
        } else {
            nw = wmin[cur][warp];
        }
        if (lane == 0) wmin[cur ^ 1][warp] = nw;
        __syncthreads();
    }

    // ---- Phase 3: gather + store (threads 0..24), R8-identical ----
    if (tid < KSEL) {
        const int   m  = (u32)mykey;
        const float d2 = __uint_as_float((u32)(mykey >> 32));

        const size_t po = (size_t)row * KSEL + tid;
        out[po * 3 + 0] = Yb[m * 3 + 0];
        out[po * 3 + 1] = Yb[m * 3 + 1];
        out[po * 3 + 2] = Yb[m * 3 + 2];
        out[O1 + po]    = (float)Ytb[m];
        out[O2 + po]    = (float)Ymb[m];
        if (tid == 0) out[O3 + row] = sqrtf(d2);
    }
}

extern "C" void kernel_launch(void* const* d_in, const int* in_sizes, int n_in,
                              void* d_out, int out_size)
{
    (void)in_sizes; (void)n_in; (void)out_size;
    const float* CB   = (const float*)d_in[0];
    const float* mask = (const float*)d_in[1];
    const float* Y    = (const float*)d_in[2];
    const int*   Yt   = (const int*)d_in[3];
    const int*   Ym   = (const int*)d_in[4];
    float* out = (float*)d_out;

    knn25_kernel<<<BB * LL, NT>>>(CB, mask, Y, Yt, Ym, out);
}